// round 8
// baseline (speedup 1.0000x reference)
#include <cuda_runtime.h>
#include <math.h>
#include <stdint.h>

#define DD 512
#define PP 36
#define PS 37                         // 36 data + mean in pad; conflict-free everywhere
#define NT 1024
#define EPSN 1e-12f
#define SCALE_CLS 7.0f
#define TILE_F (DD*PP)                // 18432 floats per gmem tile
#define SLOT_F (DD*PS)                // 18944 floats per smem slot

// SMEM float offsets (after the 3 ring slots)
#define FUSE  (3*SLOT_F)              // train fused vector [512]
#define NN    (FUSE + DD)             // per-position norms [72] (pad 80)
#define SC    (NN + 80)               // selection scores  [72]
#define WW    (SC + 80)               // fuse weights      [72]
#define RED   (WW + 80)               // reduction scratch [48]
#define SMEMF (RED + 48)
#define SMEMB (SMEMF * 4)             // 230,528 B <= 232,448 max dynamic

__device__ __forceinline__ float warp_sum(float v) {
#pragma unroll
    for (int o = 16; o > 0; o >>= 1) v += __shfl_down_sync(0xffffffffu, v, o);
    return v;
}

__device__ __forceinline__ void cp_async4(uint32_t saddr, const float* g) {
    asm volatile("cp.async.ca.shared.global [%0], [%1], 4;" :: "r"(saddr), "l"(g));
}
#define CP_COMMIT() asm volatile("cp.async.commit_group;" ::: "memory")
#define CP_WAIT1()  asm volatile("cp.async.wait_group 1;"  ::: "memory")

__global__ __launch_bounds__(NT, 1)
void fused_region_score_cp(const float* __restrict__ ftrain,
                           const float* __restrict__ ftest,
                           const int*   __restrict__ Kp,
                           float* __restrict__ out,
                           int groups, int halfOut)
{
    extern __shared__ float sm[];
    float* fuse = sm + FUSE;
    float* red  = sm + RED;

    const int tid  = threadIdx.x;
    const int lane = tid & 31;
    const int wid  = tid >> 5;           // 0..31
    const int half = tid >> 9;           // 0 = test, 1 = train
    const int d    = tid & 511;
    const int K    = Kp[0];

    const uint32_t sbase = (uint32_t)__cvta_generic_to_shared(sm);

    // contiguous group range per CTA
    const int nc = gridDim.x;
    const int q  = groups / nc, r = groups % nc;
    const int gbeg = blockIdx.x * q + min(blockIdx.x, r);
    const int gend = gbeg + q + (blockIdx.x < r ? 1 : 0);
    if (gbeg >= gend) return;
    const int tlim = 2 * gend;

    // issue one tile's cp.asyncs: 18 coalesced 4B copies per thread
    auto issue_tile = [&](int t) {
        const float* src = ((t & 1) ? ftrain : ftest) + (size_t)(t >> 1) * TILE_F;
        const uint32_t slot = sbase + (uint32_t)((t % 3) * SLOT_F) * 4u;
#pragma unroll
        for (int i = 0; i < 18; i++) {
            int e  = tid + (i << 10);    // coalesced gmem
            int dd = e / 36;
            int p  = e - dd * 36;
            cp_async4(slot + (uint32_t)(dd * PS + p) * 4u, src + e);
        }
    };

    // ---- prologue: tiles 2gb, 2gb+1, 2gb+2 in flight ----------------------
    {
        const int t0 = 2 * gbeg;
        issue_tile(t0);                 CP_COMMIT();
        issue_tile(t0 + 1);             CP_COMMIT();
        if (t0 + 2 < tlim) issue_tile(t0 + 2);
        CP_COMMIT();
    }

    for (int g = gbeg; g < gend; g++) {
        float* s_test  = sm + ((2 * g)     % 3) * SLOT_F;
        float* s_train = sm + ((2 * g + 1) % 3) * SLOT_F;
        float* mytile  = half ? s_train : s_test;

        CP_WAIT1();                     // tiles 2g, 2g+1 landed (2g+2 may fly)
        __syncthreads();                // s1: visible to all threads

        // ---- mean pass: thread (half,d) sums its row -> pad column --------
        {
            const float* row = mytile + d * PS;
            float s = 0.f;
#pragma unroll
            for (int p = 0; p < PP; p++) s += row[p];
            mytile[d * PS + PP] = s * (1.0f / PP);
        }
        __syncthreads();                // s2: means ready

        // ---- stage A partials (half 0) -------------------------------------
        if (half == 0) {
            float mt = s_test [d * PS + PP];
            float mr = s_train[d * PS + PP];
            float a = warp_sum(mt * mr);
            float b = warp_sum(mt * mt);
            float c = warp_sum(mr * mr);
            if (lane == 0) { red[wid] = a; red[16 + wid] = b; red[32 + wid] = c; }
        }

        // ---- stage B: 72 jobs (tensor,p) over 32 warps ----------------------
#pragma unroll
        for (int rr = 0; rr < 3; rr++) {
            if (rr == 2 && wid >= 8) break;
            const int j    = wid + 32 * rr;            // 0..71
            const int tens = (j >= PP) ? 1 : 0;
            const int p    = j - PP * tens;
            const float* X = tens ? s_train : s_test;
            const float* M = tens ? s_test  : s_train; // other tensor's mean (pad)
            float a2 = 0.f, ta = 0.f;
#pragma unroll
            for (int i = 0; i < DD / 32; i++) {
                int dd = lane + 32 * i;
                float a = X[dd * PS + p];
                a2 += a * a;
                ta += a * M[dd * PS + PP];
            }
            a2 = warp_sum(a2);
            ta = warp_sum(ta);
            if (lane == 0) {
                float n = fmaxf(sqrtf(a2), EPSN);
                sm[NN + j] = n;
                sm[SC + j] = ta / n;    // positive constant factors cancel in ranking
            }
        }
        __syncthreads();                // s3: SC/NN + stage-A red ready

        // ---- stage A final -------------------------------------------------
        if (wid == 0) {
            float a = (lane < 16) ? red[lane]      : 0.f;
            float b = (lane < 16) ? red[16 + lane] : 0.f;
            float c = (lane < 16) ? red[32 + lane] : 0.f;
            a = warp_sum(a); b = warp_sum(b); c = warp_sum(c);
            if (lane == 0) {
                float den = fmaxf(sqrtf(b), EPSN) * fmaxf(sqrtf(c), EPSN);
                out[g] = SCALE_CLS * a / den;
            }
        }

        // ---- stage C: top-K via rank counting -------------------------------
        if (tid < 2 * PP) {
            const int tens = (tid >= PP) ? 1 : 0;
            const int p    = tid - PP * tens;
            const int b0   = PP * tens;
            const float sv = sm[SC + tid];
            int rank = 0;
#pragma unroll
            for (int qq = 0; qq < PP; qq++) {
                float o = sm[SC + b0 + qq];
                rank += (o > sv) || (o == sv && qq < p);   // lower index wins ties
            }
            sm[WW + tid] = (rank < K) ? (1.0f / sm[NN + tid]) : 0.0f;
        }
        __syncthreads();                // s4: weights ready

        // ---- stage D: fused vector per (half,d) -----------------------------
        float u = 0.f;
        {
            const float* row = mytile + d * PS;
            const float* w   = sm + WW + half * PP;
#pragma unroll
            for (int p = 0; p < PP; p++) u += row[p] * w[p];
        }
        if (half == 1) fuse[d] = u;
        __syncthreads();                // s5: fuse ready, BOTH slots free

        // ---- refill freed slots immediately (overlaps reductions + wait) ----
        {
            const int t3 = 2 * g + 3;   // -> slot (2g)%3
            const int t4 = 2 * g + 4;   // -> slot (2g+1)%3
            if (t3 < tlim) issue_tile(t3);
            CP_COMMIT();
            if (t4 < tlim) issue_tile(t4);
            CP_COMMIT();
        }

        // ---- final score reductions (half 0) --------------------------------
        if (half == 0) {
            float v = fuse[d];
            float a = warp_sum(u * v);
            float b = warp_sum(u * u);
            float c = warp_sum(v * v);
            if (lane == 0) { red[wid] = a; red[16 + wid] = b; red[32 + wid] = c; }
        }
        __syncthreads();                // s6: red ready

        if (wid == 0) {
            float a = (lane < 16) ? red[lane]      : 0.f;
            float b = (lane < 16) ? red[16 + lane] : 0.f;
            float c = (lane < 16) ? red[32 + lane] : 0.f;
            a = warp_sum(a); b = warp_sum(b); c = warp_sum(c);
            if (lane == 0) {
                float den = fmaxf(sqrtf(b), EPSN) * fmaxf(sqrtf(c), EPSN);
                out[halfOut + g] = SCALE_CLS * a / den;
            }
        }
        // wid0's red reads precede its arrival at next s1; red next written
        // only after next s2 -> ordered without an extra barrier.
    }
}

extern "C" void kernel_launch(void* const* d_in, const int* in_sizes, int n_in,
                              void* d_out, int out_size)
{
    const float* ftrain = (const float*)d_in[0];
    const float* ftest  = (const float*)d_in[1];
    const int*   Kp     = (const int*)d_in[2];
    float* out = (float*)d_out;

    const int groups  = in_sizes[0] / (DD * PP);   // 1500
    const int halfOut = out_size / 2;              // 1500

    cudaFuncSetAttribute(fused_region_score_cp,
                         cudaFuncAttributeMaxDynamicSharedMemorySize, SMEMB);
    fused_region_score_cp<<<148, NT, SMEMB>>>(ftrain, ftest, Kp, out,
                                              groups, halfOut);
}